// round 14
// baseline (speedup 1.0000x reference)
#include <cuda_runtime.h>
#include <cuda_fp16.h>

#define NBUS 200000
#define NGEN 50000
#define NN   (NBUS + NGEN)
#define EE0  500000
#define EE1  50000
#define EE2  50000
#define EE   (EE0 + EE1 + EE2)
#define LAY  3
#define NEG  0.2f

// ---------------- static device scratch ----------------
__device__ __align__(16) float g_Wc[6][4096];   // folded node weight [l*2+t][k][j]
__device__ float g_bc[6][64];
__device__ float g_va[6][64];
__device__ float g_vb[6][64];
__device__ float g_cab[6][2];
__device__ float g_c3[9];                       // [l][etype]
__device__ __align__(16) float g_x[(size_t)NN * 64];   // unnormalized aggregate
__device__ __align__(16) __half g_p[(size_t)NN * 64];  // node message projection (fp16)
__device__ float g_a[NN];
__device__ float g_b[NN];
__device__ float g_s[NN];                       // softmax denominator
__device__ __align__(16) float g_eae[(size_t)LAY * EE * 16];   // sorted order
__device__ float g_d[(size_t)LAY * EE];         // sorted order, c3 baked in
// dst-sort scratch
__device__ int g_cnt[NN];
__device__ int g_off[NN];
__device__ int g_cur[NN];
__device__ int g_part[256];
__device__ int g_perm[EE];    // sorted pos -> original edge
__device__ int g_srcp[EE];    // sorted src
__device__ int g_dstp[EE];    // sorted dst

__device__ __forceinline__ float lrelu(float v) { return v >= 0.f ? v : NEG * v; }

// ---------------- weight folding ----------------
__global__ void prep_weights(const float* __restrict__ Wn, const float* __restrict__ bn,
                             const float* __restrict__ Wl, const float* __restrict__ bl,
                             const float* __restrict__ Watt, const float* __restrict__ Et) {
    int blk = blockIdx.x;             // l*2 + t
    int l = blk >> 1, t = blk & 1;
    __shared__ float WnS[4096], Wl1S[4096];
    const float* wn   = Wn + (size_t)blk * 4096;
    const float* wl1  = Wl + (size_t)l * 80 * 64;
    const float* watt = Watt + l * 160;
    const float* bnl  = bn + blk * 64;
    int tid = threadIdx.x;
    for (int i = tid; i < 4096; i += 256) { WnS[i] = wn[i]; Wl1S[i] = wl1[i]; }
    __syncthreads();
    for (int idx = tid; idx < 4096; idx += 256) {
        int k = idx >> 6, j = idx & 63;
        float s = 0.f;
#pragma unroll 8
        for (int m = 0; m < 64; m++) s += WnS[k * 64 + m] * Wl1S[m * 64 + j];
        g_Wc[blk][idx] = s;
    }
    if (tid < 64) {
        int j = tid;
        float s = bl[l * 64 + j];
        for (int m = 0; m < 64; m++) s += bnl[m] * Wl1S[m * 64 + j];
        g_bc[blk][j] = s;
        float sa = 0.f, sb = 0.f;
        for (int m = 0; m < 64; m++) {
            sa += WnS[j * 64 + m] * watt[m];
            sb += WnS[j * 64 + m] * watt[64 + m];
        }
        g_va[blk][j] = sa; g_vb[blk][j] = sb;
    } else if (tid == 64) {
        float ca = 0.f, cb = 0.f;
        for (int m = 0; m < 64; m++) { ca += bnl[m] * watt[m]; cb += bnl[m] * watt[64 + m]; }
        g_cab[blk][0] = ca; g_cab[blk][1] = cb;
    } else if (tid >= 128 && tid < 131 && t == 0) {
        int tt = tid - 128;
        float s = 0.f;
        for (int j = 0; j < 16; j++) s += lrelu(Et[l * 48 + tt * 16 + j]) * watt[128 + j];
        g_c3[l * 3 + tt] = s;
    }
}

// ---------------- node input embed ----------------
template <int K>
__global__ void embed_nodes(const float* __restrict__ xin, const float* __restrict__ W,
                            const float* __restrict__ bias, float* __restrict__ xout, int rows) {
    __shared__ float Ws[K * 64];
    __shared__ float bs[64];
    __shared__ float xs[4 * K];
    int tid = threadIdx.x;
    for (int i = tid; i < K * 64; i += 256) Ws[i] = W[i];
    if (tid < 64) bs[tid] = bias[tid];
    int base = blockIdx.x * 4;
    for (int i = tid; i < 4 * K; i += 256) {
        int r = base + i / K;
        xs[i] = (r < rows) ? xin[(size_t)base * K + i] : 0.f;
    }
    __syncthreads();
    int j = tid & 63, s = tid >> 6;
    int n = base + s;
    if (n < rows) {
        float acc = bs[j];
#pragma unroll
        for (int k = 0; k < K; k++) acc += xs[s * K + k] * Ws[k * 64 + j];
        xout[(size_t)n * 64 + j] = fmaxf(acc, 0.f);
    }
}

// ---------------- dst-sort build ----------------
__global__ void zero_cnt() {
    int i = blockIdx.x * 256 + threadIdx.x;
    if (i < NN) g_cnt[i] = 0;
}
__global__ void count_deg(const int* __restrict__ dst) {
    int e = blockIdx.x * 256 + threadIdx.x;
    if (e < EE) atomicAdd(&g_cnt[dst[e]], 1);
}
__global__ void scan_blocks() {
    __shared__ int sums[256];
    int tid = threadIdx.x;
    int base = blockIdx.x * 2048 + tid * 8;
    int v[8]; int s = 0;
#pragma unroll
    for (int i = 0; i < 8; i++) {
        int idx = base + i;
        v[i] = (idx < NN) ? g_cnt[idx] : 0;
        s += v[i];
    }
    sums[tid] = s;
    __syncthreads();
    for (int o = 1; o < 256; o <<= 1) {
        int t = (tid >= o) ? sums[tid - o] : 0;
        __syncthreads();
        sums[tid] += t;
        __syncthreads();
    }
    int run = (tid ? sums[tid - 1] : 0);
    if (tid == 255) g_part[blockIdx.x] = sums[255];
#pragma unroll
    for (int i = 0; i < 8; i++) {
        int idx = base + i;
        if (idx < NN) g_off[idx] = run;
        run += v[i];
    }
}
__global__ void scan_part(int nparts) {
    __shared__ int sp[256];
    int tid = threadIdx.x;
    sp[tid] = (tid < nparts) ? g_part[tid] : 0;
    __syncthreads();
    for (int o = 1; o < 256; o <<= 1) {
        int t = (tid >= o) ? sp[tid - o] : 0;
        __syncthreads();
        sp[tid] += t;
        __syncthreads();
    }
    g_part[tid] = (tid ? sp[tid - 1] : 0);
}
__global__ void scan_add() {
    int i = blockIdx.x * 256 + threadIdx.x;
    if (i < NN) g_cur[i] = g_off[i] + g_part[i >> 11];
}
__global__ void place_edges(const int* __restrict__ src, const int* __restrict__ dst) {
    int e = blockIdx.x * 256 + threadIdx.x;
    if (e >= EE) return;
    int de = dst[e];
    int pos = atomicAdd(&g_cur[de], 1);
    g_perm[pos] = e;
    g_srcp[pos] = src[e];
    g_dstp[pos] = de;
}

// ---------------- edge precompute: sorted-position order, coalesced outputs ----------------
__global__ void edge_pre(const float* __restrict__ ea0, const float* __restrict__ ea1,
                         const float* __restrict__ ea2, const float* __restrict__ W_elin,
                         const float* __restrict__ b_elin, const float* __restrict__ Wea,
                         const float* __restrict__ Watt) {
    __shared__ float We[1728];                    // [t][i][k]
    __shared__ float be[192];                     // [t][k]
    __shared__ __align__(16) float Wc48[64 * 48]; // [k][l*16+q]
    __shared__ float w4s[48];                     // [l][16]
    __shared__ float c3s[12];
    __shared__ int   permS[256];
    __shared__ float raws[256 * 9];
    int tid = threadIdx.x;
    for (int i = tid; i < 1728; i += 256) We[i] = W_elin[i];
    if (tid < 192) be[tid] = b_elin[tid];
    for (int i = tid; i < 3072; i += 256) {       // Wea[l][m][16] -> Wc48[m][l*16+q]
        int l = i >> 10, rem = i & 1023, m = rem >> 4, q = rem & 15;
        Wc48[m * 48 + l * 16 + q] = Wea[i];
    }
    if (tid < 48) w4s[tid] = Watt[(tid >> 4) * 160 + 144 + (tid & 15)];
    if (tid >= 64 && tid < 73) c3s[tid - 64] = g_c3[tid - 64];
    int base = blockIdx.x * 256;
    permS[tid] = (base + tid < EE) ? g_perm[base + tid] : 0;
    __syncthreads();
    for (int i = tid; i < 256 * 9; i += 256) {
        int j = i / 9, k = i % 9;
        float v = 0.f;
        if (base + j < EE) {
            int e = permS[j];
            if (e < EE0)            v = ea0[(size_t)e * 9 + k];
            else if (e < EE0 + EE1) v = ea1[(size_t)(e - EE0) * 9 + k];
            else                    v = ea2[(size_t)(e - EE0 - EE1) * 9 + k];
        }
        raws[i] = v;
    }
    __syncthreads();
    int jpos = base + tid;
    if (jpos >= EE) return;
    float r[9];
#pragma unroll
    for (int i = 0; i < 9; i++) r[i] = raws[tid * 9 + i];
    int e = permS[tid];
    int t = (e < EE0) ? 0 : ((e < EE0 + EE1) ? 1 : 2);
    const float* WeT = &We[t * 576];
    const float* beT = &be[t * 64];
    float4 acc[12];
#pragma unroll
    for (int j = 0; j < 12; j++) acc[j] = make_float4(0.f, 0.f, 0.f, 0.f);
#pragma unroll 2
    for (int k = 0; k < 64; k++) {
        float ea = beT[k];
#pragma unroll
        for (int i = 0; i < 9; i++) ea += r[i] * WeT[i * 64 + k];
        ea = fmaxf(ea, 0.f);
        const float4* w4 = (const float4*)&Wc48[k * 48];
#pragma unroll
        for (int j = 0; j < 12; j++) {
            float4 w = w4[j];
            acc[j].x += ea * w.x; acc[j].y += ea * w.y;
            acc[j].z += ea * w.z; acc[j].w += ea * w.w;
        }
    }
#pragma unroll
    for (int l = 0; l < 3; l++) {
        float dsum = 0.f;
#pragma unroll
        for (int q = 0; q < 4; q++) {
            float4 v = acc[l * 4 + q];
            v.x = lrelu(v.x); v.y = lrelu(v.y); v.z = lrelu(v.z); v.w = lrelu(v.w);
            float4 w = ((const float4*)w4s)[l * 4 + q];
            dsum += v.x * w.x + v.y * w.y + v.z * w.z + v.w * w.w;
            ((float4*)g_eae)[((size_t)l * EE + jpos) * 4 + q] = v;
        }
        g_d[(size_t)l * EE + jpos] = dsum + c3s[l * 3 + t];
    }
}

// ---------------- fused node GEMM: 128-row tiles, 8x4 tile; p stored fp16 ----------------
__global__ void gemm_node(const float* __restrict__ x, const float* __restrict__ sden,
                          int use_s, const float* __restrict__ Wc,
                          const float* __restrict__ bc, const float* __restrict__ va,
                          const float* __restrict__ vb, const float* __restrict__ cab,
                          __half* __restrict__ p, float* __restrict__ a, float* __restrict__ b,
                          int rows) {
    __shared__ float Ws[4096];                     // [k][j]
    __shared__ __align__(16) float xsT[64 * 132];  // [k][row], stride 132
    __shared__ float vas[64], vbs[64], bcs[64], sdiv[128];
    int tid = threadIdx.x;
    for (int i = tid; i < 4096; i += 256) Ws[i] = Wc[i];
    if (tid < 64) { vas[tid] = va[tid]; vbs[tid] = vb[tid]; bcs[tid] = bc[tid]; }
    float ca = cab[0], cb = cab[1];
    int ntiles = (rows + 127) >> 7;
    for (int tile = blockIdx.x; tile < ntiles; tile += gridDim.x) {
        int base = tile << 7;
        int cnt = min(128, rows - base);
        __syncthreads();
        if (tid < 128) {
            float sv = 1.f;
            if (use_s && tid < cnt) sv = 1.f / (sden[base + tid] + 1e-16f);
            sdiv[tid] = sv;
        }
        __syncthreads();
        for (int idx = tid; idx < 8192; idx += 256) {
            int r = idx >> 6, k = idx & 63;
            float v = (r < cnt) ? fmaxf(x[(size_t)(base + r) * 64 + k], 0.f) * sdiv[r] : 0.f;
            xsT[k * 132 + r] = v;
        }
        __syncthreads();
        int ty = tid >> 4, tx = tid & 15;
        float4 acc[8];
        {
            float4 bc4 = ((const float4*)bcs)[tx];
#pragma unroll
            for (int i = 0; i < 8; i++) acc[i] = bc4;
        }
#pragma unroll 4
        for (int k = 0; k < 64; k++) {
            float4 av0 = *(const float4*)&xsT[k * 132 + 8 * ty];
            float4 av1 = *(const float4*)&xsT[k * 132 + 8 * ty + 4];
            float4 wv = ((const float4*)Ws)[k * 16 + tx];
            acc[0].x += av0.x * wv.x; acc[0].y += av0.x * wv.y; acc[0].z += av0.x * wv.z; acc[0].w += av0.x * wv.w;
            acc[1].x += av0.y * wv.x; acc[1].y += av0.y * wv.y; acc[1].z += av0.y * wv.z; acc[1].w += av0.y * wv.w;
            acc[2].x += av0.z * wv.x; acc[2].y += av0.z * wv.y; acc[2].z += av0.z * wv.z; acc[2].w += av0.z * wv.w;
            acc[3].x += av0.w * wv.x; acc[3].y += av0.w * wv.y; acc[3].z += av0.w * wv.z; acc[3].w += av0.w * wv.w;
            acc[4].x += av1.x * wv.x; acc[4].y += av1.x * wv.y; acc[4].z += av1.x * wv.z; acc[4].w += av1.x * wv.w;
            acc[5].x += av1.y * wv.x; acc[5].y += av1.y * wv.y; acc[5].z += av1.y * wv.z; acc[5].w += av1.y * wv.w;
            acc[6].x += av1.z * wv.x; acc[6].y += av1.z * wv.y; acc[6].z += av1.z * wv.z; acc[6].w += av1.z * wv.w;
            acc[7].x += av1.w * wv.x; acc[7].y += av1.w * wv.y; acc[7].z += av1.w * wv.z; acc[7].w += av1.w * wv.w;
        }
        int r0 = 8 * ty;
#pragma unroll
        for (int i = 0; i < 8; i++) {
            if (r0 + i < cnt) {
                union { __half2 h[2]; uint2 u; } cv;
                cv.h[0] = __floats2half2_rn(acc[i].x, acc[i].y);
                cv.h[1] = __floats2half2_rn(acc[i].z, acc[i].w);
                ((uint2*)p)[(size_t)(base + r0 + i) * 16 + tx] = cv.u;
            }
        }
        int row = tid >> 1, q = tid & 1;
        float pa = 0.f, pb = 0.f;
#pragma unroll
        for (int kk = 0; kk < 32; kk++) {
            int k = q * 32 + kk;
            float v = xsT[k * 132 + row];
            pa += v * vas[k]; pb += v * vbs[k];
        }
        pa += __shfl_down_sync(0xffffffffu, pa, 1, 2);
        pb += __shfl_down_sync(0xffffffffu, pb, 1, 2);
        if (q == 0 && row < cnt) {
            a[base + row] = pa + ca;
            b[base + row] = pb + cb;
        }
    }
}

// ---------------- zero accumulator + softmax denominator ----------------
__global__ void zero_kernel(float4* __restrict__ x4, float* __restrict__ s) {
    int i = blockIdx.x * 256 + threadIdx.x;
    if (i < NN * 16) { x4[i] = make_float4(0.f, 0.f, 0.f, 0.f); return; }
    int r = i - NN * 16;
    if (r < NN) s[r] = 0.f;
}

// ---------------- fused edge pass: dst-sorted edges, fp16 p gather ----------------
#define MEPB 128
__global__ void edge_fused(const float* __restrict__ a, const float* __restrict__ b,
                           const float* __restrict__ d,
                           const __half* __restrict__ p, const float* __restrict__ eae,
                           const float* __restrict__ Wl2, const int* __restrict__ srcp,
                           const int* __restrict__ dstp, float* __restrict__ x,
                           float* __restrict__ s) {
    __shared__ float Wl2S[1024];          // [k][j] 16x64
    int tid = threadIdx.x;
    for (int i = tid; i < 1024; i += 256) Wl2S[i] = Wl2[i];
    __syncthreads();
    int sg = tid >> 4, t = tid & 15;
    int base0 = blockIdx.x * MEPB;
#pragma unroll
    for (int pass = 0; pass < MEPB / 16; pass++) {
        int e = base0 + pass * 16 + sg;
        if (e >= EE) break;
        int de = dstp[e], se = srcp[e];
        float myea = eae[(size_t)e * 16 + t];
        float lg = lrelu(a[de] + b[se] + d[e]);
        float ex = __expf(lg);
        uint2 pu = ((const uint2*)p)[(size_t)se * 16 + t];
        union { uint2 u; __half2 h[2]; } cv; cv.u = pu;
        float2 f0 = __half22float2(cv.h[0]);
        float2 f1 = __half22float2(cv.h[1]);
        float4 acc = make_float4(f0.x, f0.y, f1.x, f1.y);
#pragma unroll
        for (int k = 0; k < 16; k++) {
            float evv = __shfl_sync(0xffffffffu, myea, k, 16);
            float4 wv = ((const float4*)Wl2S)[k * 16 + t];
            acc.x += evv * wv.x; acc.y += evv * wv.y; acc.z += evv * wv.z; acc.w += evv * wv.w;
        }
        acc.x *= ex; acc.y *= ex; acc.z *= ex; acc.w *= ex;
        float* addr = x + (size_t)de * 64 + 4 * t;
        asm volatile("red.global.add.v4.f32 [%0], {%1, %2, %3, %4};"
                     :: "l"(addr), "f"(acc.x), "f"(acc.y), "f"(acc.z), "f"(acc.w)
                     : "memory");
        if (t == 0) atomicAdd(&s[de], ex);
    }
}

// ---------------- output ----------------
__global__ void out_kernel(const float* __restrict__ x, const float* __restrict__ sden,
                           const float* __restrict__ Wb, const float* __restrict__ bb,
                           const float* __restrict__ Wg, const float* __restrict__ bg,
                           float* __restrict__ out) {
    int gt = blockIdx.x * 256 + threadIdx.x;
    int n = gt >> 5, lane = gt & 31;
    if (n >= NN) return;
    float sinv = 1.f / (sden[n] + 1e-16f);
    float v0 = fmaxf(x[(size_t)n * 64 + lane], 0.f) * sinv;
    float v1 = fmaxf(x[(size_t)n * 64 + 32 + lane], 0.f) * sinv;
    const float* W = (n < NBUS) ? Wb : Wg;
    float a0 = v0 * __ldg(&W[lane * 2])     + v1 * __ldg(&W[(lane + 32) * 2]);
    float a1 = v0 * __ldg(&W[lane * 2 + 1]) + v1 * __ldg(&W[(lane + 32) * 2 + 1]);
#pragma unroll
    for (int off = 16; off; off >>= 1) {
        a0 += __shfl_down_sync(0xffffffffu, a0, off);
        a1 += __shfl_down_sync(0xffffffffu, a1, off);
    }
    if (lane == 0) {
        const float* bias = (n < NBUS) ? bb : bg;
        float z0 = a0 + bias[0], z1 = a1 + bias[1];
        out[(size_t)n * 2 + 0] = 1.f / (1.f + __expf(-z0));
        out[(size_t)n * 2 + 1] = 1.f / (1.f + __expf(-z1));
    }
}

// ---------------- host launcher ----------------
extern "C" void kernel_launch(void* const* d_in, const int* in_sizes, int n_in,
                              void* d_out, int out_size) {
    const float* x_bus     = (const float*)d_in[0];
    const float* x_gen     = (const float*)d_in[1];
    const float* ea0       = (const float*)d_in[2];
    const float* ea1       = (const float*)d_in[3];
    const float* ea2       = (const float*)d_in[4];
    const float* W_lin_bus = (const float*)d_in[5];
    const float* b_lin_bus = (const float*)d_in[6];
    const float* W_lin_gen = (const float*)d_in[7];
    const float* b_lin_gen = (const float*)d_in[8];
    const float* W_elin    = (const float*)d_in[9];
    const float* b_elin    = (const float*)d_in[10];
    const float* Wn        = (const float*)d_in[11];
    const float* bn        = (const float*)d_in[12];
    const float* Et        = (const float*)d_in[13];
    const float* Wea       = (const float*)d_in[14];
    const float* Watt      = (const float*)d_in[15];
    const float* Wl        = (const float*)d_in[16];
    const float* bl        = (const float*)d_in[17];
    const float* W_out_bus = (const float*)d_in[18];
    const float* b_out_bus = (const float*)d_in[19];
    const float* W_out_gen = (const float*)d_in[20];
    const float* b_out_gen = (const float*)d_in[21];
    const int*   src       = (const int*)d_in[22];
    const int*   dst       = (const int*)d_in[23];
    float* out = (float*)d_out;

    float *x, *a, *b, *s, *eae, *d, *Wc, *bc, *va, *vb, *cab;
    __half* p;
    int *srcp, *dstp;
    cudaGetSymbolAddress((void**)&x,    g_x);
    cudaGetSymbolAddress((void**)&p,    g_p);
    cudaGetSymbolAddress((void**)&a,    g_a);
    cudaGetSymbolAddress((void**)&b,    g_b);
    cudaGetSymbolAddress((void**)&s,    g_s);
    cudaGetSymbolAddress((void**)&eae,  g_eae);
    cudaGetSymbolAddress((void**)&d,    g_d);
    cudaGetSymbolAddress((void**)&Wc,   g_Wc);
    cudaGetSymbolAddress((void**)&bc,   g_bc);
    cudaGetSymbolAddress((void**)&va,   g_va);
    cudaGetSymbolAddress((void**)&vb,   g_vb);
    cudaGetSymbolAddress((void**)&cab,  g_cab);
    cudaGetSymbolAddress((void**)&srcp, g_srcp);
    cudaGetSymbolAddress((void**)&dstp, g_dstp);

    const int NB_NODE = (NN + 255) / 256;
    const int NB_EDGE = (EE + 255) / 256;
    const int NPARTS  = (NN + 2047) / 2048;

    // one-time precompute
    prep_weights<<<6, 256>>>(Wn, bn, Wl, bl, Watt, Et);
    embed_nodes<16><<<(NBUS + 3) / 4, 256>>>(x_bus, W_lin_bus, b_lin_bus, x, NBUS);
    embed_nodes<8> <<<(NGEN + 3) / 4, 256>>>(x_gen, W_lin_gen, b_lin_gen, x + (size_t)NBUS * 64, NGEN);
    // dst-sort build
    zero_cnt<<<NB_NODE, 256>>>();
    count_deg<<<NB_EDGE, 256>>>(dst);
    scan_blocks<<<NPARTS, 256>>>();
    scan_part<<<1, 256>>>(NPARTS);
    scan_add<<<NB_NODE, 256>>>();
    place_edges<<<NB_EDGE, 256>>>(src, dst);
    // edge features in sorted order (coalesced writes)
    edge_pre<<<NB_EDGE, 256>>>(ea0, ea1, ea2, W_elin, b_elin, Wea, Watt);

    const int TB = ((NBUS + 127) / 128 + 1) / 2;
    const int TG = ((NGEN + 127) / 128 + 1) / 2;
    for (int l = 0; l < LAY; l++) {
        int blk = l * 2;
        int use_s = (l > 0);
        gemm_node<<<TB, 256>>>(x, s, use_s, Wc + (size_t)blk * 4096,
                               bc + blk * 64, va + blk * 64, vb + blk * 64,
                               cab + blk * 2, p, a, b, NBUS);
        gemm_node<<<TG, 256>>>(x + (size_t)NBUS * 64, s + NBUS, use_s,
                               Wc + (size_t)(blk + 1) * 4096, bc + (blk + 1) * 64,
                               va + (blk + 1) * 64, vb + (blk + 1) * 64,
                               cab + (blk + 1) * 2, p + (size_t)NBUS * 64,
                               a + NBUS, b + NBUS, NGEN);
        zero_kernel<<<(NN * 16 + NN + 255) / 256, 256>>>((float4*)x, s);
        const float* Wl2 = Wl + (size_t)l * 80 * 64 + 64 * 64;
        edge_fused<<<(EE + MEPB - 1) / MEPB, 256>>>(a, b, d + (size_t)l * EE, p,
                                                    eae + (size_t)l * EE * 16, Wl2,
                                                    srcp, dstp, x, s);
    }

    out_kernel<<<((size_t)NN * 32 + 255) / 256, 256>>>(x, s, W_out_bus, b_out_bus,
                                                       W_out_gen, b_out_gen, out);
}

// round 15
// speedup vs baseline: 1.1669x; 1.1669x over previous
#include <cuda_runtime.h>
#include <cuda_fp16.h>

#define NBUS 200000
#define NGEN 50000
#define NN   (NBUS + NGEN)
#define EE0  500000
#define EE1  50000
#define EE2  50000
#define EE   (EE0 + EE1 + EE2)
#define LAY  3
#define NEG  0.2f

// ---------------- static device scratch ----------------
__device__ __align__(16) float g_Wc[6][4096];   // folded node weight [l*2+t][k][j]
__device__ float g_bc[6][64];
__device__ float g_va[6][64];
__device__ float g_vb[6][64];
__device__ float g_cab[6][2];
__device__ float g_c3[9];                       // [l][etype]
__device__ __align__(16) __half g_x[(size_t)NN * 64];  // unnormalized aggregate (fp16)
__device__ __align__(16) __half g_p[(size_t)NN * 64];  // node message projection (fp16)
__device__ float g_a[NN];
__device__ float g_b[NN];
__device__ float g_s[NN];                       // softmax denominator (fp32)
__device__ __align__(16) float g_eae[(size_t)LAY * EE * 16];   // fp32 (keep edge_pre regs low)
__device__ float g_d[(size_t)LAY * EE];         // eae.w4 + c3 baked in

__device__ __forceinline__ float lrelu(float v) { return v >= 0.f ? v : NEG * v; }

// ---------------- weight folding ----------------
__global__ void prep_weights(const float* __restrict__ Wn, const float* __restrict__ bn,
                             const float* __restrict__ Wl, const float* __restrict__ bl,
                             const float* __restrict__ Watt, const float* __restrict__ Et) {
    int blk = blockIdx.x;             // l*2 + t
    int l = blk >> 1, t = blk & 1;
    __shared__ float WnS[4096], Wl1S[4096];
    const float* wn   = Wn + (size_t)blk * 4096;
    const float* wl1  = Wl + (size_t)l * 80 * 64;
    const float* watt = Watt + l * 160;
    const float* bnl  = bn + blk * 64;
    int tid = threadIdx.x;
    for (int i = tid; i < 4096; i += 256) { WnS[i] = wn[i]; Wl1S[i] = wl1[i]; }
    __syncthreads();
    for (int idx = tid; idx < 4096; idx += 256) {
        int k = idx >> 6, j = idx & 63;
        float s = 0.f;
#pragma unroll 8
        for (int m = 0; m < 64; m++) s += WnS[k * 64 + m] * Wl1S[m * 64 + j];
        g_Wc[blk][idx] = s;
    }
    if (tid < 64) {
        int j = tid;
        float s = bl[l * 64 + j];
        for (int m = 0; m < 64; m++) s += bnl[m] * Wl1S[m * 64 + j];
        g_bc[blk][j] = s;
        float sa = 0.f, sb = 0.f;
        for (int m = 0; m < 64; m++) {
            sa += WnS[j * 64 + m] * watt[m];
            sb += WnS[j * 64 + m] * watt[64 + m];
        }
        g_va[blk][j] = sa; g_vb[blk][j] = sb;
    } else if (tid == 64) {
        float ca = 0.f, cb = 0.f;
        for (int m = 0; m < 64; m++) { ca += bnl[m] * watt[m]; cb += bnl[m] * watt[64 + m]; }
        g_cab[blk][0] = ca; g_cab[blk][1] = cb;
    } else if (tid >= 128 && tid < 131 && t == 0) {
        int tt = tid - 128;
        float s = 0.f;
        for (int j = 0; j < 16; j++) s += lrelu(Et[l * 48 + tt * 16 + j]) * watt[128 + j];
        g_c3[l * 3 + tt] = s;
    }
}

// ---------------- node input embed (writes fp16 x) ----------------
template <int K>
__global__ void embed_nodes(const float* __restrict__ xin, const float* __restrict__ W,
                            const float* __restrict__ bias, __half* __restrict__ xout, int rows) {
    __shared__ float Ws[K * 64];
    __shared__ float bs[64];
    __shared__ float xs[4 * K];
    int tid = threadIdx.x;
    for (int i = tid; i < K * 64; i += 256) Ws[i] = W[i];
    if (tid < 64) bs[tid] = bias[tid];
    int base = blockIdx.x * 4;
    for (int i = tid; i < 4 * K; i += 256) {
        int r = base + i / K;
        xs[i] = (r < rows) ? xin[(size_t)base * K + i] : 0.f;
    }
    __syncthreads();
    int j = tid & 63, s = tid >> 6;
    int n = base + s;
    if (n < rows) {
        float acc = bs[j];
#pragma unroll
        for (int k = 0; k < K; k++) acc += xs[s * K + k] * Ws[k * 64 + j];
        xout[(size_t)n * 64 + j] = __float2half(fmaxf(acc, 0.f));
    }
}

// ---------------- edge precompute: one edge per thread (byte-identical to R12) ----------------
__global__ void edge_pre(const float* __restrict__ ea0, const float* __restrict__ ea1,
                         const float* __restrict__ ea2, const float* __restrict__ W_elin,
                         const float* __restrict__ b_elin, const float* __restrict__ Wea,
                         const float* __restrict__ Watt) {
    __shared__ float We[1728];                    // [t][i][k]
    __shared__ float be[192];                     // [t][k]
    __shared__ __align__(16) float Wc48[64 * 48]; // [k][l*16+q]
    __shared__ float w4s[48];                     // [l][16]
    __shared__ float c3s[12];
    __shared__ float raws[256 * 9];
    int tid = threadIdx.x;
    for (int i = tid; i < 1728; i += 256) We[i] = W_elin[i];
    if (tid < 192) be[tid] = b_elin[tid];
    for (int i = tid; i < 3072; i += 256) {       // Wea[l][m][16] -> Wc48[m][l*16+q]
        int l = i >> 10, rem = i & 1023, m = rem >> 4, q = rem & 15;
        Wc48[m * 48 + l * 16 + q] = Wea[i];
    }
    if (tid < 48) w4s[tid] = Watt[(tid >> 4) * 160 + 144 + (tid & 15)];
    if (tid >= 64 && tid < 73) c3s[tid - 64] = g_c3[tid - 64];
    int base = blockIdx.x * 256;
    int e = base + tid;
    for (int i = tid; i < 256 * 9; i += 256) {
        int ge = base + i / 9, k = i % 9;
        float v = 0.f;
        if (ge < EE) {
            if (ge < EE0)            v = ea0[(size_t)ge * 9 + k];
            else if (ge < EE0 + EE1) v = ea1[(size_t)(ge - EE0) * 9 + k];
            else                     v = ea2[(size_t)(ge - EE0 - EE1) * 9 + k];
        }
        raws[i] = v;
    }
    __syncthreads();
    if (e >= EE) return;
    float r[9];
#pragma unroll
    for (int i = 0; i < 9; i++) r[i] = raws[tid * 9 + i];
    int t = (e < EE0) ? 0 : ((e < EE0 + EE1) ? 1 : 2);
    const float* WeT = &We[t * 576];
    const float* beT = &be[t * 64];
    float4 acc[12];
#pragma unroll
    for (int j = 0; j < 12; j++) acc[j] = make_float4(0.f, 0.f, 0.f, 0.f);
#pragma unroll 2
    for (int k = 0; k < 64; k++) {
        float ea = beT[k];
#pragma unroll
        for (int i = 0; i < 9; i++) ea += r[i] * WeT[i * 64 + k];
        ea = fmaxf(ea, 0.f);
        const float4* w4 = (const float4*)&Wc48[k * 48];
#pragma unroll
        for (int j = 0; j < 12; j++) {
            float4 w = w4[j];
            acc[j].x += ea * w.x; acc[j].y += ea * w.y;
            acc[j].z += ea * w.z; acc[j].w += ea * w.w;
        }
    }
#pragma unroll
    for (int l = 0; l < 3; l++) {
        float dsum = 0.f;
#pragma unroll
        for (int q = 0; q < 4; q++) {
            float4 v = acc[l * 4 + q];
            v.x = lrelu(v.x); v.y = lrelu(v.y); v.z = lrelu(v.z); v.w = lrelu(v.w);
            float4 w = ((const float4*)w4s)[l * 4 + q];
            dsum += v.x * w.x + v.y * w.y + v.z * w.z + v.w * w.w;
            ((float4*)g_eae)[((size_t)l * EE + e) * 4 + q] = v;
        }
        g_d[(size_t)l * EE + e] = dsum + c3s[l * 3 + t];
    }
}

// ---------------- fused node GEMM: reads fp16 x, writes fp16 p ----------------
__global__ void gemm_node(const __half* __restrict__ x, const float* __restrict__ sden,
                          int use_s, const float* __restrict__ Wc,
                          const float* __restrict__ bc, const float* __restrict__ va,
                          const float* __restrict__ vb, const float* __restrict__ cab,
                          __half* __restrict__ p, float* __restrict__ a, float* __restrict__ b,
                          int rows) {
    __shared__ float Ws[4096];                     // [k][j]
    __shared__ __align__(16) float xsT[64 * 132];  // [k][row], stride 132
    __shared__ float vas[64], vbs[64], bcs[64], sdiv[128];
    int tid = threadIdx.x;
    for (int i = tid; i < 4096; i += 256) Ws[i] = Wc[i];
    if (tid < 64) { vas[tid] = va[tid]; vbs[tid] = vb[tid]; bcs[tid] = bc[tid]; }
    float ca = cab[0], cb = cab[1];
    int ntiles = (rows + 127) >> 7;
    for (int tile = blockIdx.x; tile < ntiles; tile += gridDim.x) {
        int base = tile << 7;
        int cnt = min(128, rows - base);
        __syncthreads();
        if (tid < 128) {
            float sv = 1.f;
            if (use_s && tid < cnt) sv = 1.f / (sden[base + tid] + 1e-16f);
            sdiv[tid] = sv;
        }
        __syncthreads();
        for (int idx = tid; idx < 4096; idx += 256) {      // 2 half2 per task
            int r = idx >> 5, k2 = idx & 31;
            float2 v2 = make_float2(0.f, 0.f);
            if (r < cnt) {
                __half2 h = ((const __half2*)x)[(size_t)(base + r) * 32 + k2];
                float2 f = __half22float2(h);
                v2.x = fmaxf(f.x, 0.f) * sdiv[r];
                v2.y = fmaxf(f.y, 0.f) * sdiv[r];
            }
            xsT[(2 * k2 + 0) * 132 + r] = v2.x;
            xsT[(2 * k2 + 1) * 132 + r] = v2.y;
        }
        __syncthreads();
        int ty = tid >> 4, tx = tid & 15;
        float4 acc[8];
        {
            float4 bc4 = ((const float4*)bcs)[tx];
#pragma unroll
            for (int i = 0; i < 8; i++) acc[i] = bc4;
        }
#pragma unroll 4
        for (int k = 0; k < 64; k++) {
            float4 av0 = *(const float4*)&xsT[k * 132 + 8 * ty];
            float4 av1 = *(const float4*)&xsT[k * 132 + 8 * ty + 4];
            float4 wv = ((const float4*)Ws)[k * 16 + tx];
            acc[0].x += av0.x * wv.x; acc[0].y += av0.x * wv.y; acc[0].z += av0.x * wv.z; acc[0].w += av0.x * wv.w;
            acc[1].x += av0.y * wv.x; acc[1].y += av0.y * wv.y; acc[1].z += av0.y * wv.z; acc[1].w += av0.y * wv.w;
            acc[2].x += av0.z * wv.x; acc[2].y += av0.z * wv.y; acc[2].z += av0.z * wv.z; acc[2].w += av0.z * wv.w;
            acc[3].x += av0.w * wv.x; acc[3].y += av0.w * wv.y; acc[3].z += av0.w * wv.z; acc[3].w += av0.w * wv.w;
            acc[4].x += av1.x * wv.x; acc[4].y += av1.x * wv.y; acc[4].z += av1.x * wv.z; acc[4].w += av1.x * wv.w;
            acc[5].x += av1.y * wv.x; acc[5].y += av1.y * wv.y; acc[5].z += av1.y * wv.z; acc[5].w += av1.y * wv.w;
            acc[6].x += av1.z * wv.x; acc[6].y += av1.z * wv.y; acc[6].z += av1.z * wv.z; acc[6].w += av1.z * wv.w;
            acc[7].x += av1.w * wv.x; acc[7].y += av1.w * wv.y; acc[7].z += av1.w * wv.z; acc[7].w += av1.w * wv.w;
        }
        int r0 = 8 * ty;
#pragma unroll
        for (int i = 0; i < 8; i++) {
            if (r0 + i < cnt) {
                union { __half2 h[2]; uint2 u; } cv;
                cv.h[0] = __floats2half2_rn(acc[i].x, acc[i].y);
                cv.h[1] = __floats2half2_rn(acc[i].z, acc[i].w);
                ((uint2*)p)[(size_t)(base + r0 + i) * 16 + tx] = cv.u;
            }
        }
        int row = tid >> 1, q = tid & 1;
        float pa = 0.f, pb = 0.f;
#pragma unroll
        for (int kk = 0; kk < 32; kk++) {
            int k = q * 32 + kk;
            float v = xsT[k * 132 + row];
            pa += v * vas[k]; pb += v * vbs[k];
        }
        pa += __shfl_down_sync(0xffffffffu, pa, 1, 2);
        pb += __shfl_down_sync(0xffffffffu, pb, 1, 2);
        if (q == 0 && row < cnt) {
            a[base + row] = pa + ca;
            b[base + row] = pb + cb;
        }
    }
}

// ---------------- zero accumulator (fp16 x) + softmax denominator ----------------
__global__ void zero_kernel(float4* __restrict__ x4, float* __restrict__ s) {
    int i = blockIdx.x * 256 + threadIdx.x;
    if (i < NN * 8) { x4[i] = make_float4(0.f, 0.f, 0.f, 0.f); return; }  // NN*64 halves
    int r = i - NN * 8;
    if (r < NN) s[r] = 0.f;
}

// ---------------- fused edge pass: single red.v2.f16x2 per lane ----------------
#define MEPB 128
__global__ void edge_fused(const float* __restrict__ a, const float* __restrict__ b,
                           const float* __restrict__ d,
                           const __half* __restrict__ p, const float* __restrict__ eae,
                           const float* __restrict__ Wl2, const int* __restrict__ src,
                           const int* __restrict__ dst, __half* __restrict__ x,
                           float* __restrict__ s) {
    __shared__ float Wl2S[1024];          // [k][j] 16x64
    int tid = threadIdx.x;
    for (int i = tid; i < 1024; i += 256) Wl2S[i] = Wl2[i];
    __syncthreads();
    int sg = tid >> 4, t = tid & 15;
    int base0 = blockIdx.x * MEPB;
#pragma unroll
    for (int pass = 0; pass < MEPB / 16; pass++) {
        int e = base0 + pass * 16 + sg;
        if (e >= EE) break;
        int de = dst[e], se = src[e];
        float myea = eae[(size_t)e * 16 + t];
        float lg = lrelu(a[de] + b[se] + d[e]);
        float ex = __expf(lg);
        uint2 pu = ((const uint2*)p)[(size_t)se * 16 + t];
        union { uint2 u; __half2 h[2]; } cv; cv.u = pu;
        float2 f0 = __half22float2(cv.h[0]);
        float2 f1 = __half22float2(cv.h[1]);
        float4 acc = make_float4(f0.x, f0.y, f1.x, f1.y);
#pragma unroll
        for (int k = 0; k < 16; k++) {
            float evv = __shfl_sync(0xffffffffu, myea, k, 16);
            float4 wv = ((const float4*)Wl2S)[k * 16 + t];
            acc.x += evv * wv.x; acc.y += evv * wv.y; acc.z += evv * wv.z; acc.w += evv * wv.w;
        }
        acc.x *= ex; acc.y *= ex; acc.z *= ex; acc.w *= ex;
        union { __half2 h[2]; unsigned u[2]; } ov;
        ov.h[0] = __floats2half2_rn(acc.x, acc.y);
        ov.h[1] = __floats2half2_rn(acc.z, acc.w);
        __half* addr = x + (size_t)de * 64 + 4 * t;
        asm volatile("red.global.add.noftz.v2.f16x2 [%0], {%1, %2};"
                     :: "l"(addr), "r"(ov.u[0]), "r"(ov.u[1])
                     : "memory");
        if (t == 0) atomicAdd(&s[de], ex);
    }
}

// ---------------- output (reads fp16 x) ----------------
__global__ void out_kernel(const __half* __restrict__ x, const float* __restrict__ sden,
                           const float* __restrict__ Wb, const float* __restrict__ bb,
                           const float* __restrict__ Wg, const float* __restrict__ bg,
                           float* __restrict__ out) {
    int gt = blockIdx.x * 256 + threadIdx.x;
    int n = gt >> 5, lane = gt & 31;
    if (n >= NN) return;
    float sinv = 1.f / (sden[n] + 1e-16f);
    float v0 = fmaxf(__half2float(x[(size_t)n * 64 + lane]), 0.f) * sinv;
    float v1 = fmaxf(__half2float(x[(size_t)n * 64 + 32 + lane]), 0.f) * sinv;
    const float* W = (n < NBUS) ? Wb : Wg;
    float a0 = v0 * __ldg(&W[lane * 2])     + v1 * __ldg(&W[(lane + 32) * 2]);
    float a1 = v0 * __ldg(&W[lane * 2 + 1]) + v1 * __ldg(&W[(lane + 32) * 2 + 1]);
#pragma unroll
    for (int off = 16; off; off >>= 1) {
        a0 += __shfl_down_sync(0xffffffffu, a0, off);
        a1 += __shfl_down_sync(0xffffffffu, a1, off);
    }
    if (lane == 0) {
        const float* bias = (n < NBUS) ? bb : bg;
        float z0 = a0 + bias[0], z1 = a1 + bias[1];
        out[(size_t)n * 2 + 0] = 1.f / (1.f + __expf(-z0));
        out[(size_t)n * 2 + 1] = 1.f / (1.f + __expf(-z1));
    }
}

// ---------------- host launcher ----------------
extern "C" void kernel_launch(void* const* d_in, const int* in_sizes, int n_in,
                              void* d_out, int out_size) {
    const float* x_bus     = (const float*)d_in[0];
    const float* x_gen     = (const float*)d_in[1];
    const float* ea0       = (const float*)d_in[2];
    const float* ea1       = (const float*)d_in[3];
    const float* ea2       = (const float*)d_in[4];
    const float* W_lin_bus = (const float*)d_in[5];
    const float* b_lin_bus = (const float*)d_in[6];
    const float* W_lin_gen = (const float*)d_in[7];
    const float* b_lin_gen = (const float*)d_in[8];
    const float* W_elin    = (const float*)d_in[9];
    const float* b_elin    = (const float*)d_in[10];
    const float* Wn        = (const float*)d_in[11];
    const float* bn        = (const float*)d_in[12];
    const float* Et        = (const float*)d_in[13];
    const float* Wea       = (const float*)d_in[14];
    const float* Watt      = (const float*)d_in[15];
    const float* Wl        = (const float*)d_in[16];
    const float* bl        = (const float*)d_in[17];
    const float* W_out_bus = (const float*)d_in[18];
    const float* b_out_bus = (const float*)d_in[19];
    const float* W_out_gen = (const float*)d_in[20];
    const float* b_out_gen = (const float*)d_in[21];
    const int*   src       = (const int*)d_in[22];
    const int*   dst       = (const int*)d_in[23];
    float* out = (float*)d_out;

    float *a, *b, *s, *eae, *d, *Wc, *bc, *va, *vb, *cab;
    __half *x, *p;
    cudaGetSymbolAddress((void**)&x,   g_x);
    cudaGetSymbolAddress((void**)&p,   g_p);
    cudaGetSymbolAddress((void**)&a,   g_a);
    cudaGetSymbolAddress((void**)&b,   g_b);
    cudaGetSymbolAddress((void**)&s,   g_s);
    cudaGetSymbolAddress((void**)&eae, g_eae);
    cudaGetSymbolAddress((void**)&d,   g_d);
    cudaGetSymbolAddress((void**)&Wc,  g_Wc);
    cudaGetSymbolAddress((void**)&bc,  g_bc);
    cudaGetSymbolAddress((void**)&va,  g_va);
    cudaGetSymbolAddress((void**)&vb,  g_vb);
    cudaGetSymbolAddress((void**)&cab, g_cab);

    // one-time precompute
    prep_weights<<<6, 256>>>(Wn, bn, Wl, bl, Watt, Et);
    embed_nodes<16><<<(NBUS + 3) / 4, 256>>>(x_bus, W_lin_bus, b_lin_bus, x, NBUS);
    embed_nodes<8> <<<(NGEN + 3) / 4, 256>>>(x_gen, W_lin_gen, b_lin_gen, x + (size_t)NBUS * 64, NGEN);
    edge_pre<<<(EE + 255) / 256, 256>>>(ea0, ea1, ea2, W_elin, b_elin, Wea, Watt);

    const int TB = ((NBUS + 127) / 128 + 1) / 2;   // 2 tiles per block
    const int TG = ((NGEN + 127) / 128 + 1) / 2;
    for (int l = 0; l < LAY; l++) {
        int blk = l * 2;
        int use_s = (l > 0);
        gemm_node<<<TB, 256>>>(x, s, use_s, Wc + (size_t)blk * 4096,
                               bc + blk * 64, va + blk * 64, vb + blk * 64,
                               cab + blk * 2, p, a, b, NBUS);
        gemm_node<<<TG, 256>>>(x + (size_t)NBUS * 64, s + NBUS, use_s,
                               Wc + (size_t)(blk + 1) * 4096, bc + (blk + 1) * 64,
                               va + (blk + 1) * 64, vb + (blk + 1) * 64,
                               cab + (blk + 1) * 2, p + (size_t)NBUS * 64,
                               a + NBUS, b + NBUS, NGEN);
        zero_kernel<<<(NN * 8 + NN + 255) / 256, 256>>>((float4*)x, s);
        const float* Wl2 = Wl + (size_t)l * 80 * 64 + 64 * 64;
        edge_fused<<<(EE + MEPB - 1) / MEPB, 256>>>(a, b, d + (size_t)l * EE, p,
                                                    eae + (size_t)l * EE * 16, Wl2,
                                                    src, dst, x, s);
    }

    out_kernel<<<((size_t)NN * 32 + 255) / 256, 256>>>(x, s, W_out_bus, b_out_bus,
                                                       W_out_gen, b_out_gen, out);
}